// round 1
// baseline (speedup 1.0000x reference)
#include <cuda_runtime.h>
#include <cstdint>

#define KCH 2
#define NNODES 100000
#define ZD 128
#define FD 128
#define ROWS_TOTAL (KCH * NNODES)   // 200000
#define EDGES_MAX 1600000
#define NCHUNK ((NNODES + 1023) / 1024)   // 98

// ---------------- scratch (static device globals; allocation-free) ----------
__device__ float g_support[(size_t)ROWS_TOTAL * FD];   // 102.4 MB
__device__ int   g_count[NNODES];
__device__ int   g_rowstart[NNODES + 1];
__device__ int   g_cursor[NNODES];
__device__ int   g_blocksums[128];
__device__ int   g_csr_col[EDGES_MAX];
__device__ float g_csr_val[EDGES_MAX];

// ---------------- CSR build ----------------
__global__ void zero_count_kernel() {
    int i = blockIdx.x * blockDim.x + threadIdx.x;
    if (i < NNODES) g_count[i] = 0;
}

__global__ void hist_kernel(const int* __restrict__ rows, int E) {
    int e = blockIdx.x * blockDim.x + threadIdx.x;
    if (e < E) atomicAdd(&g_count[rows[e]], 1);
}

// inclusive scan per 1024-chunk; chunk totals -> g_blocksums
__global__ __launch_bounds__(1024) void scan1_kernel() {
    __shared__ int s[1024];
    int t = threadIdx.x;
    int idx = blockIdx.x * 1024 + t;
    int v = (idx < NNODES) ? g_count[idx] : 0;
    s[t] = v;
    __syncthreads();
#pragma unroll
    for (int off = 1; off < 1024; off <<= 1) {
        int add = (t >= off) ? s[t - off] : 0;
        __syncthreads();
        s[t] += add;
        __syncthreads();
    }
    if (idx < NNODES) g_rowstart[idx] = s[t];     // inclusive, chunk-local
    if (t == 1023) g_blocksums[blockIdx.x] = s[1023];
}

// exclusive scan of the (tiny) chunk totals
__global__ void scan2_kernel() {
    if (threadIdx.x == 0 && blockIdx.x == 0) {
        int run = 0;
        for (int b = 0; b < NCHUNK; ++b) {
            int t = g_blocksums[b];
            g_blocksums[b] = run;
            run += t;
        }
    }
}

// finalize exclusive row offsets + cursor copy
__global__ void scan3_kernel(int E) {
    int idx = blockIdx.x * blockDim.x + threadIdx.x;
    if (idx < NNODES) {
        int incl = g_rowstart[idx];
        int excl = g_blocksums[idx >> 10] + incl - g_count[idx];
        g_rowstart[idx] = excl;
        g_cursor[idx]   = excl;
    }
    if (idx == 0) g_rowstart[NNODES] = E;
}

__global__ void scatter_kernel(const int* __restrict__ rows,
                               const int* __restrict__ cols,
                               const float* __restrict__ vals, int E) {
    int e = blockIdx.x * blockDim.x + threadIdx.x;
    if (e < E) {
        int r = rows[e];
        int p = atomicAdd(&g_cursor[r], 1);
        g_csr_col[p] = cols[e];
        g_csr_val[p] = vals[e];
    }
}

// ---------------- GEMM: support[r][f] = sum_z x[r][z] * W[z][f] ------------
// Block: 256 threads, tile = 128 rows x 64 cols (2 column halves per block).
// Thread tile: 8 rows x 4 cols. W half fully staged in smem; x staged
// transposed (Xs[zz][row]) so inner-loop reads are float4 / broadcast.
__global__ __launch_bounds__(256) void gemm_kernel(const float* __restrict__ x,
                                                   const float* __restrict__ w) {
    __shared__ __align__(16) float Ws[128 * 64];    // [z][c], stride 64
    __shared__ __align__(16) float Xs[16 * 132];    // [zz][r], stride 132

    const int tid = threadIdx.x;
    const long rowbase = (long)blockIdx.x * 128;
    const int crow = (tid >> 4) * 8;   // 0..120
    const int ccol = (tid & 15) * 4;   // 0..60

    for (int half = 0; half < 2; ++half) {
        __syncthreads();
        // stage W half: 128 x 64 floats = 2048 float4, 8 per thread
#pragma unroll
        for (int j = 0; j < 8; ++j) {
            int id4 = tid + j * 256;          // 0..2047
            int z  = id4 >> 4;                // 0..127
            int c4 = (id4 & 15) << 2;         // 0..60
            float4 wv = *(const float4*)(w + (size_t)z * FD + half * 64 + c4);
            *(float4*)(Ws + z * 64 + c4) = wv;
        }

        float acc[8][4];
#pragma unroll
        for (int i = 0; i < 8; ++i)
#pragma unroll
            for (int j = 0; j < 4; ++j) acc[i][j] = 0.f;

        for (int zt = 0; zt < 128; zt += 16) {
            __syncthreads();
            // stage x tile transposed: 128 rows x 16 z
#pragma unroll
            for (int j = 0; j < 2; ++j) {
                int id = tid + j * 256;       // 0..511
                int r  = id >> 2;             // 0..127
                int q  = (id & 3) << 2;       // 0,4,8,12
                long grow = rowbase + r;
                float4 xv = make_float4(0.f, 0.f, 0.f, 0.f);
                if (grow < ROWS_TOTAL)
                    xv = *(const float4*)(x + grow * ZD + zt + q);
                Xs[(q + 0) * 132 + r] = xv.x;
                Xs[(q + 1) * 132 + r] = xv.y;
                Xs[(q + 2) * 132 + r] = xv.z;
                Xs[(q + 3) * 132 + r] = xv.w;
            }
            __syncthreads();
#pragma unroll
            for (int zz = 0; zz < 16; ++zz) {
                int z = zt + zz;
                float4 wv = *(const float4*)(Ws + z * 64 + ccol);
                float4 xa = *(const float4*)(Xs + zz * 132 + crow);
                float4 xb = *(const float4*)(Xs + zz * 132 + crow + 4);
                float xr[8] = {xa.x, xa.y, xa.z, xa.w, xb.x, xb.y, xb.z, xb.w};
#pragma unroll
                for (int i = 0; i < 8; ++i) {
                    acc[i][0] += xr[i] * wv.x;
                    acc[i][1] += xr[i] * wv.y;
                    acc[i][2] += xr[i] * wv.z;
                    acc[i][3] += xr[i] * wv.w;
                }
            }
        }
        // write back
#pragma unroll
        for (int i = 0; i < 8; ++i) {
            long grow = rowbase + crow + i;
            if (grow < ROWS_TOTAL) {
                *(float4*)(g_support + grow * FD + half * 64 + ccol) =
                    make_float4(acc[i][0], acc[i][1], acc[i][2], acc[i][3]);
            }
        }
    }
}

// ---------------- SPMM + ReLU: out[k][r][f] = relu(sum_e val*sup[k][col][f])
__global__ __launch_bounds__(128) void spmm_kernel(float* __restrict__ out) {
    const int row = blockIdx.x;
    const int k   = blockIdx.y;
    const int f   = threadIdx.x;

    const int s = g_rowstart[row];
    const int e = g_rowstart[row + 1];
    const float* __restrict__ supk = g_support + (size_t)k * NNODES * FD;

    float acc = 0.f;
    int i = s;
    for (; i + 1 < e; i += 2) {
        int   c0 = g_csr_col[i],     c1 = g_csr_col[i + 1];
        float v0 = g_csr_val[i],     v1 = g_csr_val[i + 1];
        acc += v0 * __ldg(&supk[(size_t)c0 * FD + f]);
        acc += v1 * __ldg(&supk[(size_t)c1 * FD + f]);
    }
    if (i < e) {
        int c = g_csr_col[i];
        acc += g_csr_val[i] * __ldg(&supk[(size_t)c * FD + f]);
    }
    out[((size_t)k * NNODES + row) * FD + f] = fmaxf(acc, 0.f);
}

// ---------------- launch ----------------
extern "C" void kernel_launch(void* const* d_in, const int* in_sizes, int n_in,
                              void* d_out, int out_size) {
    const float* x    = (const float*)d_in[0];
    const int*   rows = (const int*)d_in[1];
    const int*   cols = (const int*)d_in[2];
    const float* vals = (const float*)d_in[3];
    const float* w    = (const float*)d_in[4];
    float* out = (float*)d_out;
    const int E = in_sizes[1];

    zero_count_kernel<<<(NNODES + 255) / 256, 256>>>();
    hist_kernel<<<(E + 255) / 256, 256>>>(rows, E);
    scan1_kernel<<<NCHUNK, 1024>>>();
    scan2_kernel<<<1, 32>>>();
    scan3_kernel<<<(NNODES + 255) / 256, 256>>>(E);
    scatter_kernel<<<(E + 255) / 256, 256>>>(rows, cols, vals, E);
    gemm_kernel<<<(ROWS_TOTAL + 127) / 128, 256>>>(x, w);
    spmm_kernel<<<dim3(NNODES, KCH), 128>>>(out);
}

// round 3
// speedup vs baseline: 1.5692x; 1.5692x over previous
#include <cuda_runtime.h>
#include <cstdint>

#define KCH 2
#define NNODES 100000
#define ZD 128
#define FD 128
#define ROWS_TOTAL (KCH * NNODES)   // 200000
#define EDGES_MAX 1600000
#define NCHUNK ((NNODES + 1023) / 1024)   // 98

// ---------------- scratch (static device globals; allocation-free) ----------
__device__ float g_support[(size_t)ROWS_TOTAL * FD];   // 102.4 MB
__device__ int   g_count[NNODES];
__device__ int   g_rowstart[NNODES + 1];
__device__ int   g_cursor[NNODES];
__device__ int   g_blocksums[128];
__device__ int2  g_csr[EDGES_MAX];                     // (col, val bits)

// ======================= CSR build ==========================================
__global__ void zero_count_kernel() {
    int i = blockIdx.x * blockDim.x + threadIdx.x;
    if (i < NNODES) g_count[i] = 0;
}

__global__ void hist_kernel(const int* __restrict__ rows, int E) {
    int e = blockIdx.x * blockDim.x + threadIdx.x;
    if (e < E) atomicAdd(&g_count[rows[e]], 1);
}

__global__ __launch_bounds__(1024) void scan1_kernel() {
    __shared__ int s[1024];
    int t = threadIdx.x;
    int idx = blockIdx.x * 1024 + t;
    int v = (idx < NNODES) ? g_count[idx] : 0;
    s[t] = v;
    __syncthreads();
#pragma unroll
    for (int off = 1; off < 1024; off <<= 1) {
        int add = (t >= off) ? s[t - off] : 0;
        __syncthreads();
        s[t] += add;
        __syncthreads();
    }
    if (idx < NNODES) g_rowstart[idx] = s[t];
    if (t == 1023) g_blocksums[blockIdx.x] = s[1023];
}

__global__ void scan2_kernel() {
    if (threadIdx.x == 0 && blockIdx.x == 0) {
        int run = 0;
        for (int b = 0; b < NCHUNK; ++b) {
            int t = g_blocksums[b];
            g_blocksums[b] = run;
            run += t;
        }
    }
}

__global__ void scan3_kernel(int E) {
    int idx = blockIdx.x * blockDim.x + threadIdx.x;
    if (idx < NNODES) {
        int incl = g_rowstart[idx];
        int excl = g_blocksums[idx >> 10] + incl - g_count[idx];
        g_rowstart[idx] = excl;
        g_cursor[idx]   = excl;
    }
    if (idx == 0) g_rowstart[NNODES] = E;
}

__global__ void scatter_kernel(const int* __restrict__ rows,
                               const int* __restrict__ cols,
                               const float* __restrict__ vals, int E) {
    int e = blockIdx.x * blockDim.x + threadIdx.x;
    if (e < E) {
        int r = rows[e];
        int p = atomicAdd(&g_cursor[r], 1);
        g_csr[p] = make_int2(cols[e], __float_as_int(vals[e]));
    }
}

// ======================= tf32 mma.sync GEMM =================================
// support[r][f] = sum_z x[r][z] * W[z][f]
// Per CTA: 128 rows x 128 f tile, K=128. 8 warps, each warp: M32 x N64.
// Xs [row][k] stride 132, Ws [f][k] stride 132 (W transposed at staging).
// Both fragment load patterns hit banks (4g+c) mod 32 -> conflict-free.
#define SSTR 132
#define SMEM_GEMM_BYTES (2 * 128 * SSTR * 4)   // 135168

static __device__ __forceinline__ uint32_t f2tf32(float v) {
    uint32_t r;
    asm("cvt.rna.tf32.f32 %0, %1;" : "=r"(r) : "f"(v));
    return r;
}

static __device__ __forceinline__ void mma_tf32(float* d, const uint32_t* a,
                                                const uint32_t* b) {
    asm volatile(
        "mma.sync.aligned.m16n8k8.row.col.f32.tf32.tf32.f32 "
        "{%0,%1,%2,%3}, {%4,%5,%6,%7}, {%8,%9}, {%0,%1,%2,%3};\n"
        : "+f"(d[0]), "+f"(d[1]), "+f"(d[2]), "+f"(d[3])
        : "r"(a[0]), "r"(a[1]), "r"(a[2]), "r"(a[3]), "r"(b[0]), "r"(b[1]));
}

__global__ __launch_bounds__(256, 1) void gemm_mma_kernel(const float* __restrict__ x,
                                                          const float* __restrict__ w) {
    extern __shared__ float smem[];
    float* Xs = smem;                    // [128][SSTR]
    float* Ws = smem + 128 * SSTR;       // [f][SSTR] (W transposed)

    const int tid = threadIdx.x;
    const int lane = tid & 31;
    const int wid = tid >> 5;
    const long rowbase = (long)blockIdx.x * 128;

    // ---- stage x tile: [128 rows][128 k], float4 global loads, tf32 convert
#pragma unroll
    for (int it = 0; it < 16; ++it) {
        int id4 = tid + it * 256;          // 0..4095
        int r = id4 >> 5;                  // 0..127
        int q = (id4 & 31) << 2;           // 0..124
        long grow = rowbase + r;
        float4 v = make_float4(0.f, 0.f, 0.f, 0.f);
        if (grow < ROWS_TOTAL) v = *(const float4*)(x + grow * ZD + q);
        uint32_t* dst = (uint32_t*)(Xs + r * SSTR + q);
        dst[0] = f2tf32(v.x); dst[1] = f2tf32(v.y);
        dst[2] = f2tf32(v.z); dst[3] = f2tf32(v.w);
    }
    // ---- stage W transposed: Ws[f][k] = W[k][f], coalesced LDG.32
#pragma unroll
    for (int it = 0; it < 64; ++it) {
        int idx = tid + it * 256;          // 0..16383
        int k = idx >> 7;
        int f = idx & 127;
        ((uint32_t*)Ws)[f * SSTR + k] = f2tf32(w[idx]);
    }
    __syncthreads();

    // ---- compute: warp (wid>>1) owns rows [wm*32, wm*32+32),
    //               warp (wid&1) owns f [wn*64, wn*64+64)
    const int wm = wid >> 1;
    const int wn = wid & 1;
    const int g = lane >> 2;               // 0..7
    const int c = lane & 3;                // 0..3

    float acc[2][8][4];
#pragma unroll
    for (int mt = 0; mt < 2; ++mt)
#pragma unroll
        for (int nt = 0; nt < 8; ++nt)
#pragma unroll
            for (int j = 0; j < 4; ++j) acc[mt][nt][j] = 0.f;

    const uint32_t* Xw = (const uint32_t*)(Xs + (wm * 32 + g) * SSTR + c);
    const uint32_t* Ww = (const uint32_t*)(Ws + (wn * 64 + g) * SSTR + c);

#pragma unroll
    for (int ks = 0; ks < 16; ++ks) {
        const int ko = ks * 8;
        uint32_t a[2][4];
#pragma unroll
        for (int mt = 0; mt < 2; ++mt) {
            const uint32_t* p = Xw + mt * 16 * SSTR + ko;
            a[mt][0] = p[0];
            a[mt][1] = p[8 * SSTR];
            a[mt][2] = p[4];
            a[mt][3] = p[8 * SSTR + 4];
        }
        uint32_t b[8][2];
#pragma unroll
        for (int nt = 0; nt < 8; ++nt) {
            const uint32_t* p = Ww + nt * 8 * SSTR + ko;
            b[nt][0] = p[0];
            b[nt][1] = p[4];
        }
#pragma unroll
        for (int mt = 0; mt < 2; ++mt)
#pragma unroll
            for (int nt = 0; nt < 8; ++nt)
                mma_tf32(acc[mt][nt], a[mt], b[nt]);
    }

    // ---- epilogue: write D fragments (float2 per row per n-tile)
#pragma unroll
    for (int mt = 0; mt < 2; ++mt) {
        long row0 = rowbase + wm * 32 + mt * 16 + g;
        long row1 = row0 + 8;
        bool ok0 = row0 < ROWS_TOTAL;
        bool ok1 = row1 < ROWS_TOTAL;
#pragma unroll
        for (int nt = 0; nt < 8; ++nt) {
            int f = wn * 64 + nt * 8 + 2 * c;
            if (ok0)
                *(float2*)(g_support + row0 * FD + f) =
                    make_float2(acc[mt][nt][0], acc[mt][nt][1]);
            if (ok1)
                *(float2*)(g_support + row1 * FD + f) =
                    make_float2(acc[mt][nt][2], acc[mt][nt][3]);
        }
    }
}

// ======================= SPMM + ReLU ========================================
// warp per row, both K channels fused; lane owns 4 contiguous f columns
static __device__ __forceinline__ void fma4(float4& a, float v, const float4& p) {
    a.x = fmaf(v, p.x, a.x); a.y = fmaf(v, p.y, a.y);
    a.z = fmaf(v, p.z, a.z); a.w = fmaf(v, p.w, a.w);
}

__global__ __launch_bounds__(256) void spmm_kernel(float* __restrict__ out) {
    const int lid = threadIdx.x & 31;
    const int row = blockIdx.x * 8 + (threadIdx.x >> 5);
    if (row >= NNODES) return;
    const int s = g_rowstart[row];
    const int e = g_rowstart[row + 1];
    const int fo = lid << 2;
    const float* __restrict__ s0 = g_support;
    const float* __restrict__ s1 = g_support + (size_t)NNODES * FD;

    float4 a0 = make_float4(0.f, 0.f, 0.f, 0.f);
    float4 a1 = make_float4(0.f, 0.f, 0.f, 0.f);
    float4 b0 = make_float4(0.f, 0.f, 0.f, 0.f);
    float4 b1 = make_float4(0.f, 0.f, 0.f, 0.f);

    int i = s;
    for (; i + 1 < e; i += 2) {
        int2 cv0 = __ldg(&g_csr[i]);
        int2 cv1 = __ldg(&g_csr[i + 1]);
        float v0 = __int_as_float(cv0.y);
        float v1 = __int_as_float(cv1.y);
        float4 p00 = __ldg((const float4*)(s0 + (size_t)cv0.x * FD + fo));
        float4 p01 = __ldg((const float4*)(s1 + (size_t)cv0.x * FD + fo));
        float4 p10 = __ldg((const float4*)(s0 + (size_t)cv1.x * FD + fo));
        float4 p11 = __ldg((const float4*)(s1 + (size_t)cv1.x * FD + fo));
        fma4(a0, v0, p00); fma4(a1, v0, p01);
        fma4(b0, v1, p10); fma4(b1, v1, p11);
    }
    if (i < e) {
        int2 cv = __ldg(&g_csr[i]);
        float v = __int_as_float(cv.y);
        float4 p0 = __ldg((const float4*)(s0 + (size_t)cv.x * FD + fo));
        float4 p1 = __ldg((const float4*)(s1 + (size_t)cv.x * FD + fo));
        fma4(a0, v, p0); fma4(a1, v, p1);
    }
    a0.x += b0.x; a0.y += b0.y; a0.z += b0.z; a0.w += b0.w;
    a1.x += b1.x; a1.y += b1.y; a1.z += b1.z; a1.w += b1.w;

    float4 r0 = make_float4(fmaxf(a0.x, 0.f), fmaxf(a0.y, 0.f),
                            fmaxf(a0.z, 0.f), fmaxf(a0.w, 0.f));
    float4 r1 = make_float4(fmaxf(a1.x, 0.f), fmaxf(a1.y, 0.f),
                            fmaxf(a1.z, 0.f), fmaxf(a1.w, 0.f));
    *(float4*)(out + (size_t)row * FD + fo) = r0;
    *(float4*)(out + ((size_t)NNODES + row) * FD + fo) = r1;
}

// ======================= launch =============================================
extern "C" void kernel_launch(void* const* d_in, const int* in_sizes, int n_in,
                              void* d_out, int out_size) {
    const float* x    = (const float*)d_in[0];
    const int*   rows = (const int*)d_in[1];
    const int*   cols = (const int*)d_in[2];
    const float* vals = (const float*)d_in[3];
    const float* w    = (const float*)d_in[4];
    float* out = (float*)d_out;
    const int E = in_sizes[1];

    cudaFuncSetAttribute(gemm_mma_kernel,
                         cudaFuncAttributeMaxDynamicSharedMemorySize,
                         SMEM_GEMM_BYTES);

    zero_count_kernel<<<(NNODES + 255) / 256, 256>>>();
    hist_kernel<<<(E + 255) / 256, 256>>>(rows, E);
    scan1_kernel<<<NCHUNK, 1024>>>();
    scan2_kernel<<<1, 32>>>();
    scan3_kernel<<<(NNODES + 255) / 256, 256>>>(E);
    scatter_kernel<<<(E + 255) / 256, 256>>>(rows, cols, vals, E);
    gemm_mma_kernel<<<(ROWS_TOTAL + 127) / 128, 256, SMEM_GEMM_BYTES>>>(x, w);
    spmm_kernel<<<(NNODES + 7) / 8, 256>>>(out);
}

// round 4
// speedup vs baseline: 1.9857x; 1.2654x over previous
#include <cuda_runtime.h>
#include <cuda_fp16.h>
#include <cstdint>

#define KCH 2
#define NNODES 100000
#define ZD 128
#define FD 128
#define ROWS_TOTAL (KCH * NNODES)   // 200000
#define EDGES_MAX 1600000
#define NCHUNK ((NNODES + 1023) / 1024)   // 98

// ---------------- scratch (static device globals; allocation-free) ----------
__device__ __half g_support[(size_t)ROWS_TOTAL * FD];  // 51.2 MB (fp16)
__device__ int   g_count[NNODES];
__device__ int   g_rowstart[NNODES + 1];
__device__ int   g_cursor[NNODES];
__device__ int   g_blocksums[128];
__device__ int2  g_csr[EDGES_MAX];                     // (col, val bits)

// ======================= CSR build ==========================================
__global__ void zero_count_kernel() {
    int i = blockIdx.x * blockDim.x + threadIdx.x;
    if (i < NNODES) g_count[i] = 0;
}

__global__ void hist_kernel(const int* __restrict__ rows, int E) {
    int e = blockIdx.x * blockDim.x + threadIdx.x;
    if (e < E) atomicAdd(&g_count[rows[e]], 1);
}

__global__ __launch_bounds__(1024) void scan1_kernel() {
    __shared__ int s[1024];
    int t = threadIdx.x;
    int idx = blockIdx.x * 1024 + t;
    int v = (idx < NNODES) ? g_count[idx] : 0;
    s[t] = v;
    __syncthreads();
#pragma unroll
    for (int off = 1; off < 1024; off <<= 1) {
        int add = (t >= off) ? s[t - off] : 0;
        __syncthreads();
        s[t] += add;
        __syncthreads();
    }
    if (idx < NNODES) g_rowstart[idx] = s[t];
    if (t == 1023) g_blocksums[blockIdx.x] = s[1023];
}

__global__ void scan2_kernel() {
    if (threadIdx.x == 0 && blockIdx.x == 0) {
        int run = 0;
        for (int b = 0; b < NCHUNK; ++b) {
            int t = g_blocksums[b];
            g_blocksums[b] = run;
            run += t;
        }
    }
}

__global__ void scan3_kernel(int E) {
    int idx = blockIdx.x * blockDim.x + threadIdx.x;
    if (idx < NNODES) {
        int incl = g_rowstart[idx];
        int excl = g_blocksums[idx >> 10] + incl - g_count[idx];
        g_rowstart[idx] = excl;
        g_cursor[idx]   = excl;
    }
    if (idx == 0) g_rowstart[NNODES] = E;
}

__global__ void scatter_kernel(const int* __restrict__ rows,
                               const int* __restrict__ cols,
                               const float* __restrict__ vals, int E) {
    int e = blockIdx.x * blockDim.x + threadIdx.x;
    if (e < E) {
        int r = rows[e];
        int p = atomicAdd(&g_cursor[r], 1);
        g_csr[p] = make_int2(cols[e], __float_as_int(vals[e]));
    }
}

// ======================= tf32 mma.sync GEMM =================================
// support[r][f] = sum_z x[r][z] * W[z][f]   (result stored as fp16)
// Per CTA: 128 rows x 128 f tile, K=128. 8 warps, each warp: M32 x N64.
#define SSTR 132
#define SMEM_GEMM_BYTES (2 * 128 * SSTR * 4)   // 135168

static __device__ __forceinline__ uint32_t f2tf32(float v) {
    uint32_t r;
    asm("cvt.rna.tf32.f32 %0, %1;" : "=r"(r) : "f"(v));
    return r;
}

static __device__ __forceinline__ void mma_tf32(float* d, const uint32_t* a,
                                                const uint32_t* b) {
    asm volatile(
        "mma.sync.aligned.m16n8k8.row.col.f32.tf32.tf32.f32 "
        "{%0,%1,%2,%3}, {%4,%5,%6,%7}, {%8,%9}, {%0,%1,%2,%3};\n"
        : "+f"(d[0]), "+f"(d[1]), "+f"(d[2]), "+f"(d[3])
        : "r"(a[0]), "r"(a[1]), "r"(a[2]), "r"(a[3]), "r"(b[0]), "r"(b[1]));
}

__global__ __launch_bounds__(256, 1) void gemm_mma_kernel(const float* __restrict__ x,
                                                          const float* __restrict__ w) {
    extern __shared__ float smem[];
    float* Xs = smem;                    // [128][SSTR]
    float* Ws = smem + 128 * SSTR;       // [f][SSTR] (W transposed)

    const int tid = threadIdx.x;
    const int lane = tid & 31;
    const int wid = tid >> 5;
    const long rowbase = (long)blockIdx.x * 128;

    // ---- stage x tile (tf32 convert)
#pragma unroll
    for (int it = 0; it < 16; ++it) {
        int id4 = tid + it * 256;
        int r = id4 >> 5;
        int q = (id4 & 31) << 2;
        long grow = rowbase + r;
        float4 v = make_float4(0.f, 0.f, 0.f, 0.f);
        if (grow < ROWS_TOTAL) v = *(const float4*)(x + grow * ZD + q);
        uint32_t* dst = (uint32_t*)(Xs + r * SSTR + q);
        dst[0] = f2tf32(v.x); dst[1] = f2tf32(v.y);
        dst[2] = f2tf32(v.z); dst[3] = f2tf32(v.w);
    }
    // ---- stage W transposed
#pragma unroll
    for (int it = 0; it < 64; ++it) {
        int idx = tid + it * 256;
        int k = idx >> 7;
        int f = idx & 127;
        ((uint32_t*)Ws)[f * SSTR + k] = f2tf32(w[idx]);
    }
    __syncthreads();

    const int wm = wid >> 1;
    const int wn = wid & 1;
    const int g = lane >> 2;
    const int c = lane & 3;

    float acc[2][8][4];
#pragma unroll
    for (int mt = 0; mt < 2; ++mt)
#pragma unroll
        for (int nt = 0; nt < 8; ++nt)
#pragma unroll
            for (int j = 0; j < 4; ++j) acc[mt][nt][j] = 0.f;

    const uint32_t* Xw = (const uint32_t*)(Xs + (wm * 32 + g) * SSTR + c);
    const uint32_t* Ww = (const uint32_t*)(Ws + (wn * 64 + g) * SSTR + c);

#pragma unroll
    for (int ks = 0; ks < 16; ++ks) {
        const int ko = ks * 8;
        uint32_t a[2][4];
#pragma unroll
        for (int mt = 0; mt < 2; ++mt) {
            const uint32_t* p = Xw + mt * 16 * SSTR + ko;
            a[mt][0] = p[0];
            a[mt][1] = p[8 * SSTR];
            a[mt][2] = p[4];
            a[mt][3] = p[8 * SSTR + 4];
        }
        uint32_t b[8][2];
#pragma unroll
        for (int nt = 0; nt < 8; ++nt) {
            const uint32_t* p = Ww + nt * 8 * SSTR + ko;
            b[nt][0] = p[0];
            b[nt][1] = p[4];
        }
#pragma unroll
        for (int mt = 0; mt < 2; ++mt)
#pragma unroll
            for (int nt = 0; nt < 8; ++nt)
                mma_tf32(acc[mt][nt], a[mt], b[nt]);
    }

    // ---- epilogue: convert to fp16, write half2 per fragment row
#pragma unroll
    for (int mt = 0; mt < 2; ++mt) {
        long row0 = rowbase + wm * 32 + mt * 16 + g;
        long row1 = row0 + 8;
        bool ok0 = row0 < ROWS_TOTAL;
        bool ok1 = row1 < ROWS_TOTAL;
#pragma unroll
        for (int nt = 0; nt < 8; ++nt) {
            int f = wn * 64 + nt * 8 + 2 * c;
            if (ok0)
                *(__half2*)(g_support + row0 * FD + f) =
                    __float22half2_rn(make_float2(acc[mt][nt][0], acc[mt][nt][1]));
            if (ok1)
                *(__half2*)(g_support + row1 * FD + f) =
                    __float22half2_rn(make_float2(acc[mt][nt][2], acc[mt][nt][3]));
        }
    }
}

// ======================= SPMM + ReLU ========================================
// warp per row; lanes 0-15 own channel 0, lanes 16-31 own channel 1.
// Each lane owns 8 contiguous f columns: one LDG.128 (8 halves) per edge.
__global__ __launch_bounds__(256) void spmm_kernel(float* __restrict__ out) {
    const int lane = threadIdx.x & 31;
    const int row = blockIdx.x * 8 + (threadIdx.x >> 5);
    if (row >= NNODES) return;
    const int k   = lane >> 4;            // channel
    const int fo  = (lane & 15) << 3;     // f offset (8 cols)
    const int s = g_rowstart[row];
    const int e = g_rowstart[row + 1];
    const __half* __restrict__ sup = g_support + (size_t)k * NNODES * FD + fo;

    float acc[8];
#pragma unroll
    for (int j = 0; j < 8; ++j) acc[j] = 0.f;
    float accb[8];
#pragma unroll
    for (int j = 0; j < 8; ++j) accb[j] = 0.f;

    int i = s;
    for (; i + 1 < e; i += 2) {
        int2 cv0 = __ldg(&g_csr[i]);
        int2 cv1 = __ldg(&g_csr[i + 1]);
        float v0 = __int_as_float(cv0.y);
        float v1 = __int_as_float(cv1.y);
        uint4 p0 = __ldg((const uint4*)(sup + (size_t)cv0.x * FD));
        uint4 p1 = __ldg((const uint4*)(sup + (size_t)cv1.x * FD));
        const __half2* h0 = (const __half2*)&p0;
        const __half2* h1 = (const __half2*)&p1;
#pragma unroll
        for (int j = 0; j < 4; ++j) {
            float2 f0 = __half22float2(h0[j]);
            float2 f1 = __half22float2(h1[j]);
            acc[2 * j + 0]  = fmaf(v0, f0.x, acc[2 * j + 0]);
            acc[2 * j + 1]  = fmaf(v0, f0.y, acc[2 * j + 1]);
            accb[2 * j + 0] = fmaf(v1, f1.x, accb[2 * j + 0]);
            accb[2 * j + 1] = fmaf(v1, f1.y, accb[2 * j + 1]);
        }
    }
    if (i < e) {
        int2 cv = __ldg(&g_csr[i]);
        float v = __int_as_float(cv.y);
        uint4 p = __ldg((const uint4*)(sup + (size_t)cv.x * FD));
        const __half2* h = (const __half2*)&p;
#pragma unroll
        for (int j = 0; j < 4; ++j) {
            float2 f = __half22float2(h[j]);
            acc[2 * j + 0] = fmaf(v, f.x, acc[2 * j + 0]);
            acc[2 * j + 1] = fmaf(v, f.y, acc[2 * j + 1]);
        }
    }

    float* dst = out + ((size_t)k * NNODES + row) * FD + fo;
    float4 r0 = make_float4(fmaxf(acc[0] + accb[0], 0.f),
                            fmaxf(acc[1] + accb[1], 0.f),
                            fmaxf(acc[2] + accb[2], 0.f),
                            fmaxf(acc[3] + accb[3], 0.f));
    float4 r1 = make_float4(fmaxf(acc[4] + accb[4], 0.f),
                            fmaxf(acc[5] + accb[5], 0.f),
                            fmaxf(acc[6] + accb[6], 0.f),
                            fmaxf(acc[7] + accb[7], 0.f));
    *(float4*)(dst + 0) = r0;
    *(float4*)(dst + 4) = r1;
}

// ======================= launch =============================================
extern "C" void kernel_launch(void* const* d_in, const int* in_sizes, int n_in,
                              void* d_out, int out_size) {
    const float* x    = (const float*)d_in[0];
    const int*   rows = (const int*)d_in[1];
    const int*   cols = (const int*)d_in[2];
    const float* vals = (const float*)d_in[3];
    const float* w    = (const float*)d_in[4];
    float* out = (float*)d_out;
    const int E = in_sizes[1];

    cudaFuncSetAttribute(gemm_mma_kernel,
                         cudaFuncAttributeMaxDynamicSharedMemorySize,
                         SMEM_GEMM_BYTES);

    zero_count_kernel<<<(NNODES + 255) / 256, 256>>>();
    hist_kernel<<<(E + 255) / 256, 256>>>(rows, E);
    scan1_kernel<<<NCHUNK, 1024>>>();
    scan2_kernel<<<1, 32>>>();
    scan3_kernel<<<(NNODES + 255) / 256, 256>>>(E);
    scatter_kernel<<<(E + 255) / 256, 256>>>(rows, cols, vals, E);
    gemm_mma_kernel<<<(ROWS_TOTAL + 127) / 128, 256, SMEM_GEMM_BYTES>>>(x, w);
    spmm_kernel<<<(NNODES + 7) / 8, 256>>>(out);
}

// round 5
// speedup vs baseline: 2.2779x; 1.1471x over previous
#include <cuda_runtime.h>
#include <cuda_fp16.h>
#include <cstdint>

#define KCH 2
#define NNODES 100000
#define ZD 128
#define FD 128
#define ROWS_TOTAL (KCH * NNODES)   // 200000
#define EDGES_MAX 1600000
#define NCHUNK ((NNODES + 1023) / 1024)   // 98

// ---------------- scratch (static device globals; allocation-free) ----------
__device__ __half g_support[(size_t)ROWS_TOTAL * FD];  // 51.2 MB (fp16)
__device__ int   g_count[NNODES];
__device__ int   g_rowstart[NNODES + 1];
__device__ int   g_cursor[NNODES];
__device__ unsigned long long g_scanstate[NCHUNK];     // bit63 flag | total
__device__ int2  g_csr[EDGES_MAX];                     // (col, val bits)

// ======================= CSR build ==========================================
__global__ void zero_kernel() {
    int i = blockIdx.x * blockDim.x + threadIdx.x;
    if (i < NNODES) g_count[i] = 0;
    if (i < NCHUNK) g_scanstate[i] = 0ULL;
}

__global__ void hist_kernel(const int* __restrict__ rows, int E) {
    int e = blockIdx.x * blockDim.x + threadIdx.x;
    if (e < E) atomicAdd(&g_count[rows[e]], 1);
}

// fused scan: per-chunk inclusive scan + single-wave lookback over chunk totals
__global__ __launch_bounds__(1024) void scan_fused_kernel(int E) {
    __shared__ int s[1024];
    __shared__ int s_pref;
    const int t = threadIdx.x;
    const int b = blockIdx.x;
    const int idx = b * 1024 + t;
    const int v = (idx < NNODES) ? g_count[idx] : 0;
    s[t] = v;
    __syncthreads();
#pragma unroll
    for (int off = 1; off < 1024; off <<= 1) {
        int add = (t >= off) ? s[t - off] : 0;
        __syncthreads();
        s[t] += add;
        __syncthreads();
    }
    const int incl = s[t];
    // publish this chunk's total (single 64-bit word: flag rides with value)
    if (t == 1023)
        atomicExch(&g_scanstate[b], (1ULL << 63) | (unsigned long long)s[1023]);

    // warp 0: lookback-sum all predecessor totals
    if (t < 32) {
        unsigned int partial = 0;
        for (int base = 0; base < b; base += 32) {
            int j = base + t;
            unsigned int tot = 0;
            if (j < b) {
                unsigned long long w;
                do { w = atomicAdd(&g_scanstate[j], 0ULL); } while (!(w >> 63));
                tot = (unsigned int)w;
            }
            partial += tot;
        }
#pragma unroll
        for (int o = 16; o > 0; o >>= 1)
            partial += __shfl_down_sync(0xFFFFFFFFu, partial, o);
        if (t == 0) s_pref = (int)partial;
    }
    __syncthreads();
    const int excl = s_pref + incl - v;
    if (idx < NNODES) {
        g_rowstart[idx] = excl;
        g_cursor[idx]   = excl;
    }
    if (b == NCHUNK - 1 && t == 0) g_rowstart[NNODES] = E;
}

__global__ void scatter_kernel(const int* __restrict__ rows,
                               const int* __restrict__ cols,
                               const float* __restrict__ vals, int E) {
    int e = blockIdx.x * blockDim.x + threadIdx.x;
    if (e < E) {
        int r = rows[e];
        int p = atomicAdd(&g_cursor[r], 1);
        g_csr[p] = make_int2(cols[e], __float_as_int(vals[e]));
    }
}

// ======================= fp16 mma.sync GEMM =================================
// support[r][f] = sum_z x[r][z] * W[z][f]   (fp16 inputs, fp32 accum, fp16 out)
// CTA tile 128 rows x 128 f, K=128. 8 warps: warp (wid>>1) rows, (wid&1) f-half.
#define XSTR 136   // halves per row (272B): ldmatrix conflict-free
#define SMEM_GEMM_BYTES (2 * 128 * XSTR * 2)   // 69632

static __device__ __forceinline__ void ldsm_x4(uint32_t* r, uint32_t addr) {
    asm volatile("ldmatrix.sync.aligned.m8n8.x4.shared.b16 {%0,%1,%2,%3}, [%4];"
                 : "=r"(r[0]), "=r"(r[1]), "=r"(r[2]), "=r"(r[3]) : "r"(addr));
}

static __device__ __forceinline__ void mma_f16(float* d, const uint32_t* a,
                                               const uint32_t* b) {
    asm volatile(
        "mma.sync.aligned.m16n8k16.row.col.f32.f16.f16.f32 "
        "{%0,%1,%2,%3}, {%4,%5,%6,%7}, {%8,%9}, {%0,%1,%2,%3};\n"
        : "+f"(d[0]), "+f"(d[1]), "+f"(d[2]), "+f"(d[3])
        : "r"(a[0]), "r"(a[1]), "r"(a[2]), "r"(a[3]), "r"(b[0]), "r"(b[1]));
}

__global__ __launch_bounds__(256, 2) void gemm_mma_kernel(const float* __restrict__ x,
                                                          const float* __restrict__ w) {
    extern __shared__ __half smh[];
    __half* Xh = smh;                    // [128][XSTR] rows of x tile
    __half* Wh = smh + 128 * XSTR;       // [f][XSTR]  W transposed (k contiguous)

    const int tid = threadIdx.x;
    const int lane = tid & 31;
    const int wid = tid >> 5;
    const long rowbase = (long)blockIdx.x * 128;

    // ---- stage x tile: float4 loads -> half2 pairs
#pragma unroll
    for (int it = 0; it < 16; ++it) {
        int id4 = tid + it * 256;          // 0..4095
        int r = id4 >> 5;                  // 0..127
        int q = (id4 & 31) << 2;           // 0..124
        long grow = rowbase + r;
        float4 v = make_float4(0.f, 0.f, 0.f, 0.f);
        if (grow < ROWS_TOTAL) v = *(const float4*)(x + grow * ZD + q);
        __half2* dst = (__half2*)(Xh + r * XSTR + q);
        dst[0] = __floats2half2_rn(v.x, v.y);
        dst[1] = __floats2half2_rn(v.z, v.w);
    }
    // ---- stage W transposed: Wh[f][k] = W[k][f] (coalesced global reads)
#pragma unroll
    for (int it = 0; it < 64; ++it) {
        int idx = tid + it * 256;          // 0..16383
        int k = idx >> 7;
        int f = idx & 127;
        Wh[f * XSTR + k] = __float2half_rn(w[idx]);
    }
    __syncthreads();

    const int wm = wid >> 1;              // row quarter
    const int wn = wid & 1;               // f half

    float acc[2][8][4];
#pragma unroll
    for (int mt = 0; mt < 2; ++mt)
#pragma unroll
        for (int nt = 0; nt < 8; ++nt)
#pragma unroll
            for (int j = 0; j < 4; ++j) acc[mt][nt][j] = 0.f;

    // ldmatrix base addresses
    const uint32_t Xaddr = (uint32_t)__cvta_generic_to_shared(Xh);
    const uint32_t Waddr = (uint32_t)__cvta_generic_to_shared(Wh);
    // A: row = wm*32 + mt*16 + (lane&15), k = ko + (lane>>4)*8
    const uint32_t xbase = Xaddr +
        (((uint32_t)(wm * 32 + (lane & 15)) * XSTR + ((lane >> 4) << 3)) << 1);
    // B: n = wn*64 + p*16 + (lane&7) + ((lane>>4)<<3), k = ko + ((lane>>3)&1)*8
    const uint32_t wbase = Waddr +
        (((uint32_t)(wn * 64 + (lane & 7) + ((lane >> 4) << 3)) * XSTR +
          (((lane >> 3) & 1) << 3)) << 1);

#pragma unroll
    for (int ks = 0; ks < 8; ++ks) {
        const int ko = ks * 16;
        uint32_t a[2][4];
#pragma unroll
        for (int mt = 0; mt < 2; ++mt)
            ldsm_x4(a[mt], xbase + (((uint32_t)(mt * 16) * XSTR + ko) << 1));
        uint32_t b[8][2];
#pragma unroll
        for (int p = 0; p < 4; ++p) {
            uint32_t r[4];
            ldsm_x4(r, wbase + (((uint32_t)(p * 16) * XSTR + ko) << 1));
            b[2 * p][0] = r[0]; b[2 * p][1] = r[1];
            b[2 * p + 1][0] = r[2]; b[2 * p + 1][1] = r[3];
        }
#pragma unroll
        for (int mt = 0; mt < 2; ++mt)
#pragma unroll
            for (int nt = 0; nt < 8; ++nt)
                mma_f16(acc[mt][nt], a[mt], b[nt]);
    }

    // ---- epilogue: fp16 convert, half2 stores
    const int g = lane >> 2;
    const int c = lane & 3;
#pragma unroll
    for (int mt = 0; mt < 2; ++mt) {
        long row0 = rowbase + wm * 32 + mt * 16 + g;
        long row1 = row0 + 8;
        bool ok0 = row0 < ROWS_TOTAL;
        bool ok1 = row1 < ROWS_TOTAL;
#pragma unroll
        for (int nt = 0; nt < 8; ++nt) {
            int f = wn * 64 + nt * 8 + 2 * c;
            if (ok0)
                *(__half2*)(g_support + row0 * FD + f) =
                    __float22half2_rn(make_float2(acc[mt][nt][0], acc[mt][nt][1]));
            if (ok1)
                *(__half2*)(g_support + row1 * FD + f) =
                    __float22half2_rn(make_float2(acc[mt][nt][2], acc[mt][nt][3]));
        }
    }
}

// ======================= SPMM + ReLU ========================================
// warp per row; lanes 0-15 own channel 0, lanes 16-31 own channel 1.
// Each lane owns 8 contiguous f cols: one LDG.128 (8 halves) per edge.
__global__ __launch_bounds__(256) void spmm_kernel(float* __restrict__ out) {
    const int lane = threadIdx.x & 31;
    const int row = blockIdx.x * 8 + (threadIdx.x >> 5);
    if (row >= NNODES) return;
    const int k   = lane >> 4;
    const int fo  = (lane & 15) << 3;
    const int s = g_rowstart[row];
    const int e = g_rowstart[row + 1];
    const __half* __restrict__ sup = g_support + (size_t)k * NNODES * FD + fo;

    float acc[8], accb[8];
#pragma unroll
    for (int j = 0; j < 8; ++j) { acc[j] = 0.f; accb[j] = 0.f; }

    int i = s;
    for (; i + 1 < e; i += 2) {
        int2 cv0 = __ldg(&g_csr[i]);
        int2 cv1 = __ldg(&g_csr[i + 1]);
        float v0 = __int_as_float(cv0.y);
        float v1 = __int_as_float(cv1.y);
        uint4 p0 = __ldg((const uint4*)(sup + (size_t)cv0.x * FD));
        uint4 p1 = __ldg((const uint4*)(sup + (size_t)cv1.x * FD));
        const __half2* h0 = (const __half2*)&p0;
        const __half2* h1 = (const __half2*)&p1;
#pragma unroll
        for (int j = 0; j < 4; ++j) {
            float2 f0 = __half22float2(h0[j]);
            float2 f1 = __half22float2(h1[j]);
            acc[2 * j + 0]  = fmaf(v0, f0.x, acc[2 * j + 0]);
            acc[2 * j + 1]  = fmaf(v0, f0.y, acc[2 * j + 1]);
            accb[2 * j + 0] = fmaf(v1, f1.x, accb[2 * j + 0]);
            accb[2 * j + 1] = fmaf(v1, f1.y, accb[2 * j + 1]);
        }
    }
    if (i < e) {
        int2 cv = __ldg(&g_csr[i]);
        float v = __int_as_float(cv.y);
        uint4 p = __ldg((const uint4*)(sup + (size_t)cv.x * FD));
        const __half2* h = (const __half2*)&p;
#pragma unroll
        for (int j = 0; j < 4; ++j) {
            float2 f = __half22float2(h[j]);
            acc[2 * j + 0] = fmaf(v, f.x, acc[2 * j + 0]);
            acc[2 * j + 1] = fmaf(v, f.y, acc[2 * j + 1]);
        }
    }

    float* dst = out + ((size_t)k * NNODES + row) * FD + fo;
    float4 r0 = make_float4(fmaxf(acc[0] + accb[0], 0.f),
                            fmaxf(acc[1] + accb[1], 0.f),
                            fmaxf(acc[2] + accb[2], 0.f),
                            fmaxf(acc[3] + accb[3], 0.f));
    float4 r1 = make_float4(fmaxf(acc[4] + accb[4], 0.f),
                            fmaxf(acc[5] + accb[5], 0.f),
                            fmaxf(acc[6] + accb[6], 0.f),
                            fmaxf(acc[7] + accb[7], 0.f));
    *(float4*)(dst + 0) = r0;
    *(float4*)(dst + 4) = r1;
}

// ======================= launch =============================================
extern "C" void kernel_launch(void* const* d_in, const int* in_sizes, int n_in,
                              void* d_out, int out_size) {
    const float* x    = (const float*)d_in[0];
    const int*   rows = (const int*)d_in[1];
    const int*   cols = (const int*)d_in[2];
    const float* vals = (const float*)d_in[3];
    const float* w    = (const float*)d_in[4];
    float* out = (float*)d_out;
    const int E = in_sizes[1];

    cudaFuncSetAttribute(gemm_mma_kernel,
                         cudaFuncAttributeMaxDynamicSharedMemorySize,
                         SMEM_GEMM_BYTES);

    zero_kernel<<<(NNODES + 255) / 256, 256>>>();
    hist_kernel<<<(E + 255) / 256, 256>>>(rows, E);
    scan_fused_kernel<<<NCHUNK, 1024>>>(E);
    scatter_kernel<<<(E + 255) / 256, 256>>>(rows, cols, vals, E);
    gemm_mma_kernel<<<(ROWS_TOTAL + 127) / 128, 256, SMEM_GEMM_BYTES>>>(x, w);
    spmm_kernel<<<(NNODES + 7) / 8, 256>>>(out);
}

// round 6
// speedup vs baseline: 2.3040x; 1.0115x over previous
#include <cuda_runtime.h>
#include <cuda_fp16.h>
#include <cstdint>

#define KCH 2
#define NNODES 100000
#define ZD 128
#define FD 128
#define ROWS_TOTAL (KCH * NNODES)   // 200000
#define EDGES_MAX 1600000
#define NCHUNK ((NNODES + 1023) / 1024)   // 98

// ---------------- scratch (static device globals; allocation-free) ----------
__device__ __half g_support[(size_t)ROWS_TOTAL * FD];  // 51.2 MB (fp16)
__device__ int   g_count[NNODES];
__device__ int   g_rowstart[NNODES + 1];
__device__ int   g_cursor[NNODES];
__device__ unsigned long long g_scanstate[NCHUNK];     // bit63 flag | total
__device__ int2  g_csr[EDGES_MAX];                     // (col, val bits)

// ======================= small kernels ======================================
__global__ void zero_kernel() {
    int i = blockIdx.x * blockDim.x + threadIdx.x;
    if (i < NNODES) g_count[i] = 0;
    if (i < NCHUNK) g_scanstate[i] = 0ULL;
}

// histogram, 4 independent edges per thread (ILP against ATOMG latency)
__global__ __launch_bounds__(256) void hist_kernel(const int* __restrict__ rows, int E) {
    const int eb = blockIdx.x * 1024 + threadIdx.x;
    int r[4];
#pragma unroll
    for (int j = 0; j < 4; ++j) {
        int e = eb + j * 256;
        r[j] = (e < E) ? rows[e] : -1;
    }
#pragma unroll
    for (int j = 0; j < 4; ++j)
        if (r[j] >= 0) atomicAdd(&g_count[r[j]], 1);
}

// fused scan: per-chunk inclusive scan + single-wave lookback over chunk totals
__global__ __launch_bounds__(1024) void scan_fused_kernel(int E) {
    __shared__ int s[1024];
    __shared__ int s_pref;
    const int t = threadIdx.x;
    const int b = blockIdx.x;
    const int idx = b * 1024 + t;
    const int v = (idx < NNODES) ? g_count[idx] : 0;
    s[t] = v;
    __syncthreads();
#pragma unroll
    for (int off = 1; off < 1024; off <<= 1) {
        int add = (t >= off) ? s[t - off] : 0;
        __syncthreads();
        s[t] += add;
        __syncthreads();
    }
    const int incl = s[t];
    if (t == 1023)
        atomicExch(&g_scanstate[b], (1ULL << 63) | (unsigned long long)s[1023]);

    if (t < 32) {
        unsigned int partial = 0;
        for (int base = 0; base < b; base += 32) {
            int j = base + t;
            unsigned int tot = 0;
            if (j < b) {
                unsigned long long w;
                do { w = atomicAdd(&g_scanstate[j], 0ULL); } while (!(w >> 63));
                tot = (unsigned int)w;
            }
            partial += tot;
        }
#pragma unroll
        for (int o = 16; o > 0; o >>= 1)
            partial += __shfl_down_sync(0xFFFFFFFFu, partial, o);
        if (t == 0) s_pref = (int)partial;
    }
    __syncthreads();
    const int excl = s_pref + incl - v;
    if (idx < NNODES) {
        g_rowstart[idx] = excl;
        g_cursor[idx]   = excl;
    }
    if (b == NCHUNK - 1 && t == 0) g_rowstart[NNODES] = E;
}

// ======================= fused GEMM + scatter ===============================
// Blocks [0, ngemm): fp16 mma GEMM tile. Blocks [ngemm, ...): CSR scatter.
// Independent work items sharing one launch -> they overlap on the SMs.
#define XSTR 136
#define SMEM_GEMM_BYTES (2 * 128 * XSTR * 2)   // 69632

static __device__ __forceinline__ void ldsm_x4(uint32_t* r, uint32_t addr) {
    asm volatile("ldmatrix.sync.aligned.m8n8.x4.shared.b16 {%0,%1,%2,%3}, [%4];"
                 : "=r"(r[0]), "=r"(r[1]), "=r"(r[2]), "=r"(r[3]) : "r"(addr));
}

static __device__ __forceinline__ void mma_f16(float* d, const uint32_t* a,
                                               const uint32_t* b) {
    asm volatile(
        "mma.sync.aligned.m16n8k16.row.col.f32.f16.f16.f32 "
        "{%0,%1,%2,%3}, {%4,%5,%6,%7}, {%8,%9}, {%0,%1,%2,%3};\n"
        : "+f"(d[0]), "+f"(d[1]), "+f"(d[2]), "+f"(d[3])
        : "r"(a[0]), "r"(a[1]), "r"(a[2]), "r"(a[3]), "r"(b[0]), "r"(b[1]));
}

__global__ __launch_bounds__(256, 2) void gemm_scatter_kernel(
    const float* __restrict__ x, const float* __restrict__ w,
    const int* __restrict__ rows, const int* __restrict__ cols,
    const float* __restrict__ vals, int E, int ngemm) {
    extern __shared__ __half smh[];
    const int tid = threadIdx.x;

    if (blockIdx.x >= ngemm) {
        // ---------------- scatter path (no smem use) ----------------
        const int eb = (blockIdx.x - ngemm) * 1024 + tid;
        int r[4], c[4];
        float v[4];
#pragma unroll
        for (int j = 0; j < 4; ++j) {
            int e = eb + j * 256;
            if (e < E) { r[j] = rows[e]; c[j] = cols[e]; v[j] = vals[e]; }
            else       { r[j] = -1; c[j] = 0; v[j] = 0.f; }
        }
        int p[4];
#pragma unroll
        for (int j = 0; j < 4; ++j)
            p[j] = (r[j] >= 0) ? atomicAdd(&g_cursor[r[j]], 1) : 0;
#pragma unroll
        for (int j = 0; j < 4; ++j)
            if (r[j] >= 0) g_csr[p[j]] = make_int2(c[j], __float_as_int(v[j]));
        return;
    }

    // ---------------- GEMM path ----------------
    __half* Xh = smh;                    // [128][XSTR]
    __half* Wh = smh + 128 * XSTR;       // [f][XSTR] (W transposed)
    const int lane = tid & 31;
    const int wid = tid >> 5;
    const long rowbase = (long)blockIdx.x * 128;

#pragma unroll
    for (int it = 0; it < 16; ++it) {
        int id4 = tid + it * 256;
        int rr = id4 >> 5;
        int q = (id4 & 31) << 2;
        long grow = rowbase + rr;
        float4 vv = make_float4(0.f, 0.f, 0.f, 0.f);
        if (grow < ROWS_TOTAL) vv = *(const float4*)(x + grow * ZD + q);
        __half2* dst = (__half2*)(Xh + rr * XSTR + q);
        dst[0] = __floats2half2_rn(vv.x, vv.y);
        dst[1] = __floats2half2_rn(vv.z, vv.w);
    }
#pragma unroll
    for (int it = 0; it < 64; ++it) {
        int idx = tid + it * 256;
        int k = idx >> 7;
        int f = idx & 127;
        Wh[f * XSTR + k] = __float2half_rn(w[idx]);
    }
    __syncthreads();

    const int wm = wid >> 1;
    const int wn = wid & 1;

    float acc[2][8][4];
#pragma unroll
    for (int mt = 0; mt < 2; ++mt)
#pragma unroll
        for (int nt = 0; nt < 8; ++nt)
#pragma unroll
            for (int j = 0; j < 4; ++j) acc[mt][nt][j] = 0.f;

    const uint32_t Xaddr = (uint32_t)__cvta_generic_to_shared(Xh);
    const uint32_t Waddr = (uint32_t)__cvta_generic_to_shared(Wh);
    const uint32_t xbase = Xaddr +
        (((uint32_t)(wm * 32 + (lane & 15)) * XSTR + ((lane >> 4) << 3)) << 1);
    const uint32_t wbase = Waddr +
        (((uint32_t)(wn * 64 + (lane & 7) + ((lane >> 4) << 3)) * XSTR +
          (((lane >> 3) & 1) << 3)) << 1);

#pragma unroll
    for (int ks = 0; ks < 8; ++ks) {
        const int ko = ks * 16;
        uint32_t a[2][4];
#pragma unroll
        for (int mt = 0; mt < 2; ++mt)
            ldsm_x4(a[mt], xbase + (((uint32_t)(mt * 16) * XSTR + ko) << 1));
        uint32_t b[8][2];
#pragma unroll
        for (int p = 0; p < 4; ++p) {
            uint32_t rr[4];
            ldsm_x4(rr, wbase + (((uint32_t)(p * 16) * XSTR + ko) << 1));
            b[2 * p][0] = rr[0]; b[2 * p][1] = rr[1];
            b[2 * p + 1][0] = rr[2]; b[2 * p + 1][1] = rr[3];
        }
#pragma unroll
        for (int mt = 0; mt < 2; ++mt)
#pragma unroll
            for (int nt = 0; nt < 8; ++nt)
                mma_f16(acc[mt][nt], a[mt], b[nt]);
    }

    const int g = lane >> 2;
    const int c = lane & 3;
#pragma unroll
    for (int mt = 0; mt < 2; ++mt) {
        long row0 = rowbase + wm * 32 + mt * 16 + g;
        long row1 = row0 + 8;
        bool ok0 = row0 < ROWS_TOTAL;
        bool ok1 = row1 < ROWS_TOTAL;
#pragma unroll
        for (int nt = 0; nt < 8; ++nt) {
            int f = wn * 64 + nt * 8 + 2 * c;
            if (ok0)
                *(__half2*)(g_support + row0 * FD + f) =
                    __float22half2_rn(make_float2(acc[mt][nt][0], acc[mt][nt][1]));
            if (ok1)
                *(__half2*)(g_support + row1 * FD + f) =
                    __float22half2_rn(make_float2(acc[mt][nt][2], acc[mt][nt][3]));
        }
    }
}

// ======================= SPMM + ReLU ========================================
__global__ __launch_bounds__(256) void spmm_kernel(float* __restrict__ out) {
    const int lane = threadIdx.x & 31;
    const int row = blockIdx.x * 8 + (threadIdx.x >> 5);
    if (row >= NNODES) return;
    const int k   = lane >> 4;
    const int fo  = (lane & 15) << 3;
    const int s = g_rowstart[row];
    const int e = g_rowstart[row + 1];
    const __half* __restrict__ sup = g_support + (size_t)k * NNODES * FD + fo;

    float acc[8], accb[8];
#pragma unroll
    for (int j = 0; j < 8; ++j) { acc[j] = 0.f; accb[j] = 0.f; }

    int i = s;
    for (; i + 1 < e; i += 2) {
        int2 cv0 = __ldg(&g_csr[i]);
        int2 cv1 = __ldg(&g_csr[i + 1]);
        float v0 = __int_as_float(cv0.y);
        float v1 = __int_as_float(cv1.y);
        uint4 p0 = __ldg((const uint4*)(sup + (size_t)cv0.x * FD));
        uint4 p1 = __ldg((const uint4*)(sup + (size_t)cv1.x * FD));
        const __half2* h0 = (const __half2*)&p0;
        const __half2* h1 = (const __half2*)&p1;
#pragma unroll
        for (int j = 0; j < 4; ++j) {
            float2 f0 = __half22float2(h0[j]);
            float2 f1 = __half22float2(h1[j]);
            acc[2 * j + 0]  = fmaf(v0, f0.x, acc[2 * j + 0]);
            acc[2 * j + 1]  = fmaf(v0, f0.y, acc[2 * j + 1]);
            accb[2 * j + 0] = fmaf(v1, f1.x, accb[2 * j + 0]);
            accb[2 * j + 1] = fmaf(v1, f1.y, accb[2 * j + 1]);
        }
    }
    if (i < e) {
        int2 cv = __ldg(&g_csr[i]);
        float v = __int_as_float(cv.y);
        uint4 p = __ldg((const uint4*)(sup + (size_t)cv.x * FD));
        const __half2* h = (const __half2*)&p;
#pragma unroll
        for (int j = 0; j < 4; ++j) {
            float2 f = __half22float2(h[j]);
            acc[2 * j + 0] = fmaf(v, f.x, acc[2 * j + 0]);
            acc[2 * j + 1] = fmaf(v, f.y, acc[2 * j + 1]);
        }
    }

    float* dst = out + ((size_t)k * NNODES + row) * FD + fo;
    float4 r0 = make_float4(fmaxf(acc[0] + accb[0], 0.f),
                            fmaxf(acc[1] + accb[1], 0.f),
                            fmaxf(acc[2] + accb[2], 0.f),
                            fmaxf(acc[3] + accb[3], 0.f));
    float4 r1 = make_float4(fmaxf(acc[4] + accb[4], 0.f),
                            fmaxf(acc[5] + accb[5], 0.f),
                            fmaxf(acc[6] + accb[6], 0.f),
                            fmaxf(acc[7] + accb[7], 0.f));
    *(float4*)(dst + 0) = r0;
    *(float4*)(dst + 4) = r1;
}

// ======================= launch =============================================
extern "C" void kernel_launch(void* const* d_in, const int* in_sizes, int n_in,
                              void* d_out, int out_size) {
    const float* x    = (const float*)d_in[0];
    const int*   rows = (const int*)d_in[1];
    const int*   cols = (const int*)d_in[2];
    const float* vals = (const float*)d_in[3];
    const float* w    = (const float*)d_in[4];
    float* out = (float*)d_out;
    const int E = in_sizes[1];

    cudaFuncSetAttribute(gemm_scatter_kernel,
                         cudaFuncAttributeMaxDynamicSharedMemorySize,
                         SMEM_GEMM_BYTES);

    const int ngemm = (ROWS_TOTAL + 127) / 128;
    const int nscat = (E + 1023) / 1024;

    zero_kernel<<<(NNODES + 255) / 256, 256>>>();
    hist_kernel<<<(E + 1023) / 1024, 256>>>(rows, E);
    scan_fused_kernel<<<NCHUNK, 1024>>>(E);
    gemm_scatter_kernel<<<ngemm + nscat, 256, SMEM_GEMM_BYTES>>>(
        x, w, rows, cols, vals, E, ngemm);
    spmm_kernel<<<(NNODES + 7) / 8, 256>>>(out);
}

// round 7
// speedup vs baseline: 2.4805x; 1.0766x over previous
#include <cuda_runtime.h>
#include <cuda_fp16.h>
#include <cstdint>

#define KCH 2
#define NNODES 100000
#define ZD 128
#define FD 128
#define ROWS_TOTAL (KCH * NNODES)   // 200000
#define EDGES_MAX 1600000
#define NCHUNK ((NNODES + 1023) / 1024)   // 98

// ---------------- scratch (static device globals; allocation-free) ----------
__device__ __half g_support[(size_t)ROWS_TOTAL * FD];  // 51.2 MB (fp16)
__device__ __half g_wh[FD * ZD];                       // W transposed fp16 [f][k]
__device__ int   g_count[NNODES];
__device__ int   g_rowstart[NNODES + 1];
__device__ int   g_cursor[NNODES];
__device__ unsigned long long g_scanstate[NCHUNK];     // bit63 flag | total
__device__ int2  g_csr[EDGES_MAX];                     // (col, val bits)

// ======================= zero + W pre-convert ===============================
__global__ void zero_kernel(const float* __restrict__ w) {
    int i = blockIdx.x * blockDim.x + threadIdx.x;
    if (i < NNODES) g_count[i] = 0;
    if (i < NCHUNK) g_scanstate[i] = 0ULL;
    if (i < FD * ZD) {
        int f = i >> 7, k = i & 127;
        g_wh[i] = __float2half_rn(w[k * FD + f]);   // g_wh[f][k] = W[k][f]
    }
}

// histogram: 4 edges per thread via int4 load (ILP vs ATOMG latency)
__global__ __launch_bounds__(256) void hist_kernel(const int* __restrict__ rows, int E) {
    const int e = (blockIdx.x * 256 + threadIdx.x) * 4;
    if (e + 3 < E) {
        int4 r = *(const int4*)(rows + e);
        atomicAdd(&g_count[r.x], 1);
        atomicAdd(&g_count[r.y], 1);
        atomicAdd(&g_count[r.z], 1);
        atomicAdd(&g_count[r.w], 1);
    } else {
        for (int j = e; j < E; ++j) atomicAdd(&g_count[rows[j]], 1);
    }
}

// fused scan: per-chunk inclusive scan + single-wave lookback over chunk totals
__global__ __launch_bounds__(1024) void scan_fused_kernel(int E) {
    __shared__ int s[1024];
    __shared__ int s_pref;
    const int t = threadIdx.x;
    const int b = blockIdx.x;
    const int idx = b * 1024 + t;
    const int v = (idx < NNODES) ? g_count[idx] : 0;
    s[t] = v;
    __syncthreads();
#pragma unroll
    for (int off = 1; off < 1024; off <<= 1) {
        int add = (t >= off) ? s[t - off] : 0;
        __syncthreads();
        s[t] += add;
        __syncthreads();
    }
    const int incl = s[t];
    if (t == 1023)
        atomicExch(&g_scanstate[b], (1ULL << 63) | (unsigned long long)s[1023]);

    if (t < 32) {
        unsigned int partial = 0;
        for (int base = 0; base < b; base += 32) {
            int j = base + t;
            unsigned int tot = 0;
            if (j < b) {
                unsigned long long w;
                do { w = atomicAdd(&g_scanstate[j], 0ULL); } while (!(w >> 63));
                tot = (unsigned int)w;
            }
            partial += tot;
        }
#pragma unroll
        for (int o = 16; o > 0; o >>= 1)
            partial += __shfl_down_sync(0xFFFFFFFFu, partial, o);
        if (t == 0) s_pref = (int)partial;
    }
    __syncthreads();
    const int excl = s_pref + incl - v;
    if (idx < NNODES) {
        g_rowstart[idx] = excl;
        g_cursor[idx]   = excl;
    }
    if (b == NCHUNK - 1 && t == 0) g_rowstart[NNODES] = E;
}

// ======================= fused GEMM + scatter ===============================
#define XSTR 136
#define SMEM_GEMM_BYTES (2 * 128 * XSTR * 2)   // 69632

static __device__ __forceinline__ void ldsm_x4(uint32_t* r, uint32_t addr) {
    asm volatile("ldmatrix.sync.aligned.m8n8.x4.shared.b16 {%0,%1,%2,%3}, [%4];"
                 : "=r"(r[0]), "=r"(r[1]), "=r"(r[2]), "=r"(r[3]) : "r"(addr));
}

static __device__ __forceinline__ void mma_f16(float* d, const uint32_t* a,
                                               const uint32_t* b) {
    asm volatile(
        "mma.sync.aligned.m16n8k16.row.col.f32.f16.f16.f32 "
        "{%0,%1,%2,%3}, {%4,%5,%6,%7}, {%8,%9}, {%0,%1,%2,%3};\n"
        : "+f"(d[0]), "+f"(d[1]), "+f"(d[2]), "+f"(d[3])
        : "r"(a[0]), "r"(a[1]), "r"(a[2]), "r"(a[3]), "r"(b[0]), "r"(b[1]));
}

__global__ __launch_bounds__(256, 2) void gemm_scatter_kernel(
    const float* __restrict__ x,
    const int* __restrict__ rows, const int* __restrict__ cols,
    const float* __restrict__ vals, int E, int ngemm) {
    extern __shared__ __half smh[];
    const int tid = threadIdx.x;

    if (blockIdx.x >= ngemm) {
        // ---------------- scatter path ----------------
        const int e = ((blockIdx.x - ngemm) * 256 + tid) * 4;
        if (e + 3 < E) {
            int4 r = *(const int4*)(rows + e);
            int4 c = *(const int4*)(cols + e);
            float4 v = *(const float4*)(vals + e);
            int p0 = atomicAdd(&g_cursor[r.x], 1);
            int p1 = atomicAdd(&g_cursor[r.y], 1);
            int p2 = atomicAdd(&g_cursor[r.z], 1);
            int p3 = atomicAdd(&g_cursor[r.w], 1);
            g_csr[p0] = make_int2(c.x, __float_as_int(v.x));
            g_csr[p1] = make_int2(c.y, __float_as_int(v.y));
            g_csr[p2] = make_int2(c.z, __float_as_int(v.z));
            g_csr[p3] = make_int2(c.w, __float_as_int(v.w));
        } else {
            for (int j = e; j < E; ++j) {
                int p = atomicAdd(&g_cursor[rows[j]], 1);
                g_csr[p] = make_int2(cols[j], __float_as_int(vals[j]));
            }
        }
        return;
    }

    // ---------------- GEMM path ----------------
    __half* Xh = smh;                    // [128][XSTR]
    __half* Wh = smh + 128 * XSTR;       // [f][XSTR] fp16 W^T from g_wh
    const int lane = tid & 31;
    const int wid = tid >> 5;
    const long rowbase = (long)blockIdx.x * 128;

    // stage x tile: float4 loads -> half2 pairs
#pragma unroll
    for (int it = 0; it < 16; ++it) {
        int id4 = tid + it * 256;
        int rr = id4 >> 5;
        int q = (id4 & 31) << 2;
        long grow = rowbase + rr;
        float4 vv = make_float4(0.f, 0.f, 0.f, 0.f);
        if (grow < ROWS_TOTAL) vv = *(const float4*)(x + grow * ZD + q);
        __half2* dst = (__half2*)(Xh + rr * XSTR + q);
        dst[0] = __floats2half2_rn(vv.x, vv.y);
        dst[1] = __floats2half2_rn(vv.z, vv.w);
    }
    // stage W^T: pre-converted fp16, 8x uint4 per thread
#pragma unroll
    for (int it = 0; it < 8; ++it) {
        int idx = tid + it * 256;          // 0..2047
        int f = idx >> 4;
        int seg = (idx & 15) << 3;         // half offset, mult of 8
        *(uint4*)(Wh + f * XSTR + seg) = *(const uint4*)(g_wh + f * ZD + seg);
    }
    __syncthreads();

    const int wm = wid >> 1;
    const int wn = wid & 1;

    float acc[2][8][4];
#pragma unroll
    for (int mt = 0; mt < 2; ++mt)
#pragma unroll
        for (int nt = 0; nt < 8; ++nt)
#pragma unroll
            for (int j = 0; j < 4; ++j) acc[mt][nt][j] = 0.f;

    const uint32_t Xaddr = (uint32_t)__cvta_generic_to_shared(Xh);
    const uint32_t Waddr = (uint32_t)__cvta_generic_to_shared(Wh);
    const uint32_t xbase = Xaddr +
        (((uint32_t)(wm * 32 + (lane & 15)) * XSTR + ((lane >> 4) << 3)) << 1);
    const uint32_t wbase = Waddr +
        (((uint32_t)(wn * 64 + (lane & 7) + ((lane >> 4) << 3)) * XSTR +
          (((lane >> 3) & 1) << 3)) << 1);

#pragma unroll
    for (int ks = 0; ks < 8; ++ks) {
        const int ko = ks * 16;
        uint32_t a[2][4];
#pragma unroll
        for (int mt = 0; mt < 2; ++mt)
            ldsm_x4(a[mt], xbase + (((uint32_t)(mt * 16) * XSTR + ko) << 1));
        uint32_t b[8][2];
#pragma unroll
        for (int p = 0; p < 4; ++p) {
            uint32_t rr[4];
            ldsm_x4(rr, wbase + (((uint32_t)(p * 16) * XSTR + ko) << 1));
            b[2 * p][0] = rr[0]; b[2 * p][1] = rr[1];
            b[2 * p + 1][0] = rr[2]; b[2 * p + 1][1] = rr[3];
        }
#pragma unroll
        for (int mt = 0; mt < 2; ++mt)
#pragma unroll
            for (int nt = 0; nt < 8; ++nt)
                mma_f16(acc[mt][nt], a[mt], b[nt]);
    }

    const int g = lane >> 2;
    const int c = lane & 3;
#pragma unroll
    for (int mt = 0; mt < 2; ++mt) {
        long row0 = rowbase + wm * 32 + mt * 16 + g;
        long row1 = row0 + 8;
        bool ok0 = row0 < ROWS_TOTAL;
        bool ok1 = row1 < ROWS_TOTAL;
#pragma unroll
        for (int nt = 0; nt < 8; ++nt) {
            int f = wn * 64 + nt * 8 + 2 * c;
            if (ok0)
                *(__half2*)(g_support + row0 * FD + f) =
                    __float22half2_rn(make_float2(acc[mt][nt][0], acc[mt][nt][1]));
            if (ok1)
                *(__half2*)(g_support + row1 * FD + f) =
                    __float22half2_rn(make_float2(acc[mt][nt][2], acc[mt][nt][3]));
        }
    }
}

// ======================= SPMM + ReLU ========================================
// warp per row; lanes 0-15 ch0, lanes 16-31 ch1; lane owns 8 f cols.
// 4 independent edges in flight per iteration.
__global__ __launch_bounds__(256) void spmm_kernel(float* __restrict__ out) {
    const int lane = threadIdx.x & 31;
    const int row = blockIdx.x * 8 + (threadIdx.x >> 5);
    if (row >= NNODES) return;
    const int k   = lane >> 4;
    const int fo  = (lane & 15) << 3;
    const int s = g_rowstart[row];
    const int e = g_rowstart[row + 1];
    const __half* __restrict__ sup = g_support + (size_t)k * NNODES * FD + fo;

    float acc[8], accb[8];
#pragma unroll
    for (int j = 0; j < 8; ++j) { acc[j] = 0.f; accb[j] = 0.f; }

    int i = s;
    for (; i + 3 < e; i += 4) {
        int2 cv0 = __ldg(&g_csr[i]);
        int2 cv1 = __ldg(&g_csr[i + 1]);
        int2 cv2 = __ldg(&g_csr[i + 2]);
        int2 cv3 = __ldg(&g_csr[i + 3]);
        uint4 p0 = __ldg((const uint4*)(sup + (size_t)cv0.x * FD));
        uint4 p1 = __ldg((const uint4*)(sup + (size_t)cv1.x * FD));
        uint4 p2 = __ldg((const uint4*)(sup + (size_t)cv2.x * FD));
        uint4 p3 = __ldg((const uint4*)(sup + (size_t)cv3.x * FD));
        float v0 = __int_as_float(cv0.y);
        float v1 = __int_as_float(cv1.y);
        float v2 = __int_as_float(cv2.y);
        float v3 = __int_as_float(cv3.y);
        const __half2* h0 = (const __half2*)&p0;
        const __half2* h1 = (const __half2*)&p1;
        const __half2* h2 = (const __half2*)&p2;
        const __half2* h3 = (const __half2*)&p3;
#pragma unroll
        for (int j = 0; j < 4; ++j) {
            float2 f0 = __half22float2(h0[j]);
            float2 f1 = __half22float2(h1[j]);
            float2 f2 = __half22float2(h2[j]);
            float2 f3 = __half22float2(h3[j]);
            acc[2 * j + 0]  = fmaf(v0, f0.x, acc[2 * j + 0]);
            acc[2 * j + 1]  = fmaf(v0, f0.y, acc[2 * j + 1]);
            accb[2 * j + 0] = fmaf(v1, f1.x, accb[2 * j + 0]);
            accb[2 * j + 1] = fmaf(v1, f1.y, accb[2 * j + 1]);
            acc[2 * j + 0]  = fmaf(v2, f2.x, acc[2 * j + 0]);
            acc[2 * j + 1]  = fmaf(v2, f2.y, acc[2 * j + 1]);
            accb[2 * j + 0] = fmaf(v3, f3.x, accb[2 * j + 0]);
            accb[2 * j + 1] = fmaf(v3, f3.y, accb[2 * j + 1]);
        }
    }
    for (; i < e; ++i) {
        int2 cv = __ldg(&g_csr[i]);
        float v = __int_as_float(cv.y);
        uint4 p = __ldg((const uint4*)(sup + (size_t)cv.x * FD));
        const __half2* h = (const __half2*)&p;
#pragma unroll
        for (int j = 0; j < 4; ++j) {
            float2 f = __half22float2(h[j]);
            acc[2 * j + 0] = fmaf(v, f.x, acc[2 * j + 0]);
            acc[2 * j + 1] = fmaf(v, f.y, acc[2 * j + 1]);
        }
    }

    float* dst = out + ((size_t)k * NNODES + row) * FD + fo;
    float4 r0 = make_float4(fmaxf(acc[0] + accb[0], 0.f),
                            fmaxf(acc[1] + accb[1], 0.f),
                            fmaxf(acc[2] + accb[2], 0.f),
                            fmaxf(acc[3] + accb[3], 0.f));
    float4 r1 = make_float4(fmaxf(acc[4] + accb[4], 0.f),
                            fmaxf(acc[5] + accb[5], 0.f),
                            fmaxf(acc[6] + accb[6], 0.f),
                            fmaxf(acc[7] + accb[7], 0.f));
    *(float4*)(dst + 0) = r0;
    *(float4*)(dst + 4) = r1;
}

// ======================= launch =============================================
extern "C" void kernel_launch(void* const* d_in, const int* in_sizes, int n_in,
                              void* d_out, int out_size) {
    const float* x    = (const float*)d_in[0];
    const int*   rows = (const int*)d_in[1];
    const int*   cols = (const int*)d_in[2];
    const float* vals = (const float*)d_in[3];
    const float* w    = (const float*)d_in[4];
    float* out = (float*)d_out;
    const int E = in_sizes[1];

    cudaFuncSetAttribute(gemm_scatter_kernel,
                         cudaFuncAttributeMaxDynamicSharedMemorySize,
                         SMEM_GEMM_BYTES);

    const int ngemm = (ROWS_TOTAL + 127) / 128;
    const int nscat = (E + 1023) / 1024;

    zero_kernel<<<(NNODES + 255) / 256, 256>>>(w);
    hist_kernel<<<(E + 1023) / 1024, 256>>>(rows, E);
    scan_fused_kernel<<<NCHUNK, 1024>>>(E);
    gemm_scatter_kernel<<<ngemm + nscat, 256, SMEM_GEMM_BYTES>>>(
        x, rows, cols, vals, E, ngemm);
    spmm_kernel<<<(NNODES + 7) / 8, 256>>>(out);
}